// round 3
// baseline (speedup 1.0000x reference)
#include <cuda_runtime.h>
#include <cuda_bf16.h>
#include <cstddef>

// Problem constants
#define BSZ  64
#define TT   512
#define DD   1024
#define HH   1024
#define H4   4096
#define BT   (BSZ*TT)          // 32768
#define NBLK 128               // persistent grid size (64 col-tiles x 2 row-tiles)

// Scratch (device globals — allocation-free per harness rules)
__device__ float g_xz[(size_t)BT * H4];     // per-layer input-GEMM result (reused)
__device__ float g_out0[(size_t)BT * HH];   // layer-0 hidden outputs (B,T,H)
__device__ float g_h0[BSZ * HH];
__device__ float g_h1[BSZ * HH];

// grid-barrier state
__device__ unsigned g_bar_count = 0;
__device__ volatile unsigned g_bar_gen = 0;

__device__ __forceinline__ void grid_barrier()
{
    __syncthreads();
    if (threadIdx.x == 0) {
        __threadfence();                       // publish this block's stores
        unsigned gen = g_bar_gen;              // read BEFORE arriving
        if (atomicAdd(&g_bar_count, 1u) == NBLK - 1) {
            atomicExch(&g_bar_count, 0u);
            __threadfence();
            g_bar_gen = gen + 1;               // release
        } else {
            while (g_bar_gen == gen) { }       // volatile spin
        }
    }
    __syncthreads();
}

// ---------------------------------------------------------------------------
// Classic 128x128x8 SGEMM with bias: C[M,4096] = A[M,K] @ B[K,4096] + bias
// grid = (N/128, M/128), 256 threads, 8x8 per thread.
// ---------------------------------------------------------------------------
__global__ __launch_bounds__(256) void sgemm_bias(
    const float* __restrict__ A, const float* __restrict__ Bm,
    const float* __restrict__ bias, float* __restrict__ C, int K)
{
    const int N = H4;
    __shared__ float As[8][128];
    __shared__ float Bs[8][128];

    const int tid = threadIdx.x;
    const int tx = tid & 15;
    const int ty = tid >> 4;

    const float* Ab = A + (size_t)blockIdx.y * 128 * K;
    const float* Bb = Bm + blockIdx.x * 128;

    const int arow = tid >> 1;
    const int ak   = (tid & 1) * 4;
    const int bk   = tid >> 5;
    const int bcol = (tid & 31) * 4;

    float acc[8][8];
#pragma unroll
    for (int i = 0; i < 8; i++)
#pragma unroll
        for (int j = 0; j < 8; j++) acc[i][j] = 0.f;

    for (int k0 = 0; k0 < K; k0 += 8) {
        float4 av = *(const float4*)(Ab + (size_t)arow * K + k0 + ak);
        As[ak + 0][arow] = av.x;
        As[ak + 1][arow] = av.y;
        As[ak + 2][arow] = av.z;
        As[ak + 3][arow] = av.w;
        float4 bv = *(const float4*)(Bb + (size_t)(k0 + bk) * N + bcol);
        *(float4*)&Bs[bk][bcol] = bv;
        __syncthreads();
#pragma unroll
        for (int kk = 0; kk < 8; kk++) {
            float a[8], b[8];
            *(float4*)(a)     = *(float4*)&As[kk][ty * 8];
            *(float4*)(a + 4) = *(float4*)&As[kk][ty * 8 + 4];
            *(float4*)(b)     = *(float4*)&Bs[kk][tx * 8];
            *(float4*)(b + 4) = *(float4*)&Bs[kk][tx * 8 + 4];
#pragma unroll
            for (int i = 0; i < 8; i++)
#pragma unroll
                for (int j = 0; j < 8; j++)
                    acc[i][j] = fmaf(a[i], b[j], acc[i][j]);
        }
        __syncthreads();
    }

    const int crow0 = blockIdx.y * 128 + ty * 8;
    const int ccol0 = blockIdx.x * 128 + tx * 8;
#pragma unroll
    for (int i = 0; i < 8; i++) {
        float* crow = C + (size_t)(crow0 + i) * N + ccol0;
#pragma unroll
        for (int j = 0; j < 8; j += 4) {
            float4 v;
            v.x = acc[i][j + 0] + bias[ccol0 + j + 0];
            v.y = acc[i][j + 1] + bias[ccol0 + j + 1];
            v.z = acc[i][j + 2] + bias[ccol0 + j + 2];
            v.w = acc[i][j + 3] + bias[ccol0 + j + 3];
            *(float4*)(crow + j) = v;
        }
    }
}

// ---------------------------------------------------------------------------
// Persistent LSTM layer: all 512 timesteps in one launch.
// grid = (HH/16, BSZ/32) = (64,2) = 128 blocks, 128 threads.
// Block: 32 batch rows x 16 h-cols x 4 gates. Thread: 4 rows x 1 col x 4 gates.
// c and own-h kept in registers across steps; cross-block h via ping-pong
// global buffers read with __ldcg (L1 is not coherent across SMs).
// ---------------------------------------------------------------------------
__global__ __launch_bounds__(128) void lstm_layer(
    const float* __restrict__ xz, const float* __restrict__ U,
    const int* __restrict__ lengths,
    float* __restrict__ hb0, float* __restrict__ hb1,
    float* __restrict__ out, float* __restrict__ finalHC)
{
    const int col0 = blockIdx.x * 16;
    const int row0 = blockIdx.y * 32;
    const int tid  = threadIdx.x;
    const int cx = tid & 15;
    const int rg = tid >> 4;

    __shared__ float hs[16][33];   // [k][row], padded
    __shared__ float us[16][64];   // [k][gate*16 + col]

    const int lrow = tid >> 2;        // 0..31
    const int lk   = (tid & 3) * 4;   // 0,4,8,12
    const int s    = tid >> 1;        // 0..63
    const int skk  = s >> 2;          // 0..15
    const int sg   = s & 3;           // gate 0..3
    const int half = (tid & 1) * 8;

    // per-thread persistent state
    float creg[4], hreg[4];
    int   lenr[4];
#pragma unroll
    for (int r = 0; r < 4; r++) {
        creg[r] = 0.f;
        hreg[r] = 0.f;
        const int row = row0 + rg * 4 + r;
        lenr[r] = lengths[row];
        hb0[row * HH + col0 + cx] = 0.f;   // zero-init shared h buffer
    }
    grid_barrier();

    for (int t = 0; t < TT; t++) {
        const float* hprev = (t & 1) ? hb1 : hb0;
        float*       hnext = (t & 1) ? hb0 : hb1;

        float acc[4][4];
#pragma unroll
        for (int g = 0; g < 4; g++)
#pragma unroll
            for (int r = 0; r < 4; r++) acc[g][r] = 0.f;

        for (int k0 = 0; k0 < HH; k0 += 16) {
            // h tile (32 rows x 16 k), transposed into smem; L2-coherent load
            float4 hv4 = __ldcg((const float4*)(hprev + (size_t)(row0 + lrow) * HH + k0 + lk));
            hs[lk + 0][lrow] = hv4.x;
            hs[lk + 1][lrow] = hv4.y;
            hs[lk + 2][lrow] = hv4.z;
            hs[lk + 3][lrow] = hv4.w;
            // U tile (16 k x 16 cols x 4 gates)
            const float* up = U + (size_t)(k0 + skk) * H4 + sg * HH + col0 + half;
            float4 u0 = *(const float4*)(up);
            float4 u1 = *(const float4*)(up + 4);
            *(float4*)&us[skk][sg * 16 + half]     = u0;
            *(float4*)&us[skk][sg * 16 + half + 4] = u1;
            __syncthreads();
#pragma unroll
            for (int kk = 0; kk < 16; kk++) {
                const float uv0 = us[kk][cx];
                const float uv1 = us[kk][16 + cx];
                const float uv2 = us[kk][32 + cx];
                const float uv3 = us[kk][48 + cx];
#pragma unroll
                for (int r = 0; r < 4; r++) {
                    const float hv = hs[kk][rg * 4 + r];
                    acc[0][r] = fmaf(hv, uv0, acc[0][r]);
                    acc[1][r] = fmaf(hv, uv1, acc[1][r]);
                    acc[2][r] = fmaf(hv, uv2, acc[2][r]);
                    acc[3][r] = fmaf(hv, uv3, acc[3][r]);
                }
            }
            __syncthreads();
        }

        const int col = col0 + cx;
#pragma unroll
        for (int r = 0; r < 4; r++) {
            const int row = row0 + rg * 4 + r;
            const size_t xrow = ((size_t)row * TT + t) * H4;
            const float zi = xz[xrow +          col] + acc[0][r];
            const float zf = xz[xrow + HH     + col] + acc[1][r];
            const float zg = xz[xrow + 2 * HH + col] + acc[2][r];
            const float zo = xz[xrow + 3 * HH + col] + acc[3][r];
            const float ig = 1.f / (1.f + __expf(-zi));
            const float fg = 1.f / (1.f + __expf(-zf));
            const float gg = tanhf(zg);
            const float og = 1.f / (1.f + __expf(-zo));
            const float cn = fg * creg[r] + ig * gg;
            const float hn = og * tanhf(cn);
            const bool m = t < lenr[r];
            const float h2 = m ? hn : hreg[r];
            const float c2 = m ? cn : creg[r];
            creg[r] = c2;
            hreg[r] = h2;
            hnext[row * HH + col] = h2;
            out[((size_t)row * TT + t) * HH + col] = h2;
        }
        grid_barrier();
    }

    if (finalHC) {
#pragma unroll
        for (int r = 0; r < 4; r++) {
            const int idx = (row0 + rg * 4 + r) * HH + col0 + cx;
            finalHC[idx]            = hreg[r];
            finalHC[BSZ * HH + idx] = creg[r];
        }
    }
}

// ---------------------------------------------------------------------------
extern "C" void kernel_launch(void* const* d_in, const int* in_sizes, int n_in,
                              void* d_out, int out_size)
{
    const float* x   = (const float*)d_in[0];   // (B,T,D)
    const int*   len = (const int*)  d_in[1];   // (B,)
    const float* W0  = (const float*)d_in[2];   // (D,4H)
    const float* U0  = (const float*)d_in[3];   // (H,4H)
    const float* b0  = (const float*)d_in[4];   // (4H,)
    const float* W1  = (const float*)d_in[5];   // (H,4H)
    const float* U1  = (const float*)d_in[6];   // (H,4H)
    const float* b1  = (const float*)d_in[7];   // (4H,)
    float* outf = (float*)d_out;                // rnnout | h | c

    float *xz, *out0, *h0, *h1;
    cudaGetSymbolAddress((void**)&xz,   g_xz);
    cudaGetSymbolAddress((void**)&out0, g_out0);
    cudaGetSymbolAddress((void**)&h0,   g_h0);
    cudaGetSymbolAddress((void**)&h1,   g_h1);

    const dim3 gGemm(H4 / 128, BT / 128);  // (32, 256)
    const dim3 gStep(HH / 16, BSZ / 32);   // (64, 2) = 128 blocks

    // ---- Layer 0 ----
    sgemm_bias<<<gGemm, 256>>>(x, W0, b0, xz, DD);
    lstm_layer<<<gStep, 128>>>(xz, U0, len, h0, h1, out0, nullptr);

    // ---- Layer 1 ----
    sgemm_bias<<<gGemm, 256>>>(out0, W1, b1, xz, HH);
    lstm_layer<<<gStep, 128>>>(xz, U1, len, h0, h1, outf, outf + (size_t)BT * HH);
}